// round 7
// baseline (speedup 1.0000x reference)
#include <cuda_runtime.h>
#include <cstdint>

#define B_   16
#define N_   4096
#define M_   1024
#define KNN_ 32
#define P_   (B_*M_*KNN_)   // 524288

typedef unsigned long long ull;

// ---------------- device scratch (no allocation allowed) ----------------
__device__ float g_featT[B_*N_*64];      // [b][n][c]
__device__ int   g_idx[P_];
__device__ float g_y1[P_*64];
__device__ float g_y2[P_*64];
__device__ float g_y3[P_*128ull];
__device__ float g_p1s[4096*64], g_p1q[4096*64];
__device__ float g_p2s[4096*64], g_p2q[4096*64];
__device__ float g_p3s[8192*128], g_p3q[8192*128];
__device__ float g_bn1[128];   // [0:64) scale, [64:128) shift
__device__ float g_bn2[128];
__device__ float g_bn3[256];

// ---------------- f32x2 helpers ----------------
__device__ __forceinline__ ull pk(float a, float b) {
    ull r; asm("mov.b64 %0, {%1, %2};" : "=l"(r) : "f"(a), "f"(b)); return r;
}
__device__ __forceinline__ void fma2(ull& d, ull a, ull b) {
    asm("fma.rn.f32x2 %0, %1, %2, %0;" : "+l"(d) : "l"(a), "l"(b));
}
__device__ __forceinline__ float2 unpk(ull v) {
    float2 f; asm("mov.b64 {%0, %1}, %2;" : "=f"(f.x), "=f"(f.y) : "l"(v)); return f;
}

// ---------------- transpose features [b][c][n] -> [b][n][c] ----------------
__global__ void k_transpose(const float* __restrict__ f) {
    __shared__ float t[32][33];
    int n0 = blockIdx.x * 32, c0 = blockIdx.y * 32, b = blockIdx.z;
    int tx = threadIdx.x, ty = threadIdx.y;
#pragma unroll
    for (int i = 0; i < 4; i++)
        t[ty + i*8][tx] = f[((size_t)b*64 + c0 + ty + i*8) * N_ + n0 + tx];
    __syncthreads();
#pragma unroll
    for (int i = 0; i < 4; i++)
        g_featT[((size_t)b*N_ + n0 + ty + i*8) * 64 + c0 + tx] = t[tx][ty + i*8];
}

// ---------------- exact KNN: radix-select smallest-32 ----------------
__device__ __forceinline__ unsigned fkey(float f) {
    unsigned u = __float_as_uint(f);
    return (u & 0x80000000u) ? ~u : (u | 0x80000000u);
}

__global__ void k_knn(const float* __restrict__ loc, const float* __restrict__ nl) {
    __shared__ unsigned keys[N_];
    __shared__ unsigned hist[256];
    __shared__ unsigned sh_pfx;
    __shared__ int sh_r, sh_no, sh_ne;
    __shared__ int outb[32];
    __shared__ int eqb[128];
    int tid = threadIdx.x, m = blockIdx.x, b = blockIdx.y;

    float qx = nl[(b*M_+m)*3+0], qy = nl[(b*M_+m)*3+1], qz = nl[(b*M_+m)*3+2];
    float q2 = qx*qx + qy*qy + qz*qz;
    for (int i = tid; i < N_; i += 128) {
        float lx = loc[(b*N_+i)*3+0], ly = loc[(b*N_+i)*3+1], lz = loc[(b*N_+i)*3+2];
        float x2 = lx*lx + ly*ly + lz*lz;
        float dot = qx*lx + qy*ly + qz*lz;
        keys[i] = fkey(q2 + x2 - 2.0f*dot);
    }
    if (tid == 0) { sh_pfx = 0u; sh_r = 31; sh_no = 0; sh_ne = 0; }
    __syncthreads();

    for (int sh = 24; sh >= 0; sh -= 8) {
        for (int i = tid; i < 256; i += 128) hist[i] = 0u;
        __syncthreads();
        unsigned pfx = sh_pfx;
        unsigned hm = (sh == 24) ? 0u : (0xFFFFFFFFu << (sh + 8));
        for (int i = tid; i < N_; i += 128) {
            unsigned k = keys[i];
            if ((k & hm) == pfx) atomicAdd(&hist[(k >> sh) & 255], 1u);
        }
        __syncthreads();
        if (tid == 0) {
            int r = sh_r; unsigned c = 0;
            for (int d = 0; d < 256; d++) {
                unsigned h = hist[d];
                if (c + h > (unsigned)r) { sh_pfx = pfx | ((unsigned)d << sh); sh_r = r - (int)c; break; }
                c += h;
            }
        }
        __syncthreads();
    }
    unsigned T = sh_pfx;
    for (int i = tid; i < N_; i += 128) {
        unsigned k = keys[i];
        if (k < T) { int p = atomicAdd(&sh_no, 1); outb[p] = i; }
        else if (k == T) { int p = atomicAdd(&sh_ne, 1); if (p < 128) eqb[p] = i; }
    }
    __syncthreads();
    if (tid == 0) {
        int need = 32 - sh_no, ne = sh_ne < 128 ? sh_ne : 128;
        for (int t = 0; t < need; t++) {
            int best = 0x7fffffff, bj = 0;
            for (int j = 0; j < ne; j++) if (eqb[j] < best) { best = eqb[j]; bj = j; }
            outb[sh_no + t] = best; eqb[bj] = 0x7fffffff;
        }
    }
    __syncthreads();
    if (tid < 32) {   // deterministic order: rank-sort by index
        int v = outb[tid], rank = 0;
#pragma unroll
        for (int j = 0; j < 32; j++) rank += (outb[j] < v);
        g_idx[((b*M_+m) << 5) + rank] = v;
    }
}

// ---------------- shared GEMM + BN-partial epilogue ----------------
// 256 threads, thread tile 8 positions x 4 outputs.
template<int CIN, int CO, int TP>
__device__ __forceinline__ void gemm_epi(float* A, const float* W,
                                         float* yout, float* ps, float* pq, int p0) {
    const int OG = CO/4, PG = TP/8, AS = TP + 4;
    int tid = threadIdx.x;
    int og = tid % OG, pg = tid / OG;
    int o0 = og*4, pp = pg*8;
    ull acc[8][2];
#pragma unroll
    for (int i = 0; i < 8; i++) { acc[i][0] = 0ull; acc[i][1] = 0ull; }
#pragma unroll 4
    for (int c = 0; c < CIN; c++) {
        float4 w = *(const float4*)&W[c*CO + o0];
        ull w01 = pk(w.x, w.y), w23 = pk(w.z, w.w);
        float av[8];
        *(float4*)&av[0] = *(const float4*)&A[c*AS + pp];
        *(float4*)&av[4] = *(const float4*)&A[c*AS + pp + 4];
#pragma unroll
        for (int i = 0; i < 8; i++) {
            ull t = pk(av[i], av[i]);
            fma2(acc[i][0], t, w01); fma2(acc[i][1], t, w23);
        }
    }
    float s[4] = {0,0,0,0}, q[4] = {0,0,0,0};
#pragma unroll
    for (int i = 0; i < 8; i++) {
        float2 u0 = unpk(acc[i][0]), u1 = unpk(acc[i][1]);
        float4 r = make_float4(u0.x, u0.y, u1.x, u1.y);
        *(float4*)&yout[(size_t)(p0 + pp + i)*CO + o0] = r;
        s[0] += r.x; q[0] += r.x*r.x; s[1] += r.y; q[1] += r.y*r.y;
        s[2] += r.z; q[2] += r.z*r.z; s[3] += r.w; q[3] += r.w*r.w;
    }
    __syncthreads();                    // A no longer needed: reuse as reduce buf
    float* rs = A; float* rq = A + PG*CO;
#pragma unroll
    for (int j = 0; j < 4; j++) { rs[pg*CO + o0 + j] = s[j]; rq[pg*CO + o0 + j] = q[j]; }
    __syncthreads();
    if (tid < CO) {
        float S = 0, Q = 0;
#pragma unroll
        for (int g = 0; g < PG; g++) { S += rs[g*CO + tid]; Q += rq[g*CO + tid]; }
        ps[blockIdx.x*CO + tid] = S; pq[blockIdx.x*CO + tid] = Q;
    }
}

// ---------------- stage 1: gather [3 rel-xyz | 64 feat | pad] -> W1 ----------------
__global__ void k_stage1(const float* __restrict__ loc, const float* __restrict__ nl,
                         const float* __restrict__ W1) {
    extern __shared__ float sm[];
    float* A = sm; float* Wsh = sm + 68*132;
    int tid = threadIdx.x;
    for (int i = tid; i < 68*64; i += 256) {
        int c = i >> 6, o = i & 63;
        Wsh[i] = (c < 67) ? W1[o*67 + c] : 0.0f;
    }
    int p0 = blockIdx.x * 128;
    int pr = tid >> 1, half = tid & 1;
    int p = p0 + pr;
    int n = g_idx[p];
    int m = (p >> 5) & (M_-1);
    int b = p >> 15;
    if (half == 0) {
#pragma unroll
        for (int d = 0; d < 3; d++)
            A[d*132 + pr] = loc[(b*N_+n)*3 + d] - nl[(b*M_+m)*3 + d];
        A[67*132 + pr] = 0.0f;
    }
    const float4* fsrc = (const float4*)(g_featT + ((size_t)(b*N_+n))*64 + half*32);
#pragma unroll
    for (int j = 0; j < 8; j++) {
        float4 v = fsrc[j]; int c = 3 + half*32 + j*4;
        A[(c+0)*132 + pr] = v.x; A[(c+1)*132 + pr] = v.y;
        A[(c+2)*132 + pr] = v.z; A[(c+3)*132 + pr] = v.w;
    }
    __syncthreads();
    gemm_epi<68,64,128>(A, Wsh, g_y1, g_p1s, g_p1q, p0);
}

// ---------------- stages 2/3: BN+ReLU(yin) -> W ----------------
template<int CO, int TP>
__global__ void k_stageN(const float* __restrict__ yin, const float* __restrict__ W,
                         const float* __restrict__ bn, float* yout, float* ps, float* pq) {
    const int AS = TP + 4;
    extern __shared__ float sm[];
    float* A = sm; float* Wsh = sm + 64*AS;
    __shared__ float sc[64], sb[64];
    int tid = threadIdx.x;
    if (tid < 64) { sc[tid] = bn[tid]; sb[tid] = bn[64 + tid]; }
    for (int i = tid; i < 64*CO; i += 256) {
        int c = i / CO, o = i % CO;
        Wsh[i] = W[o*64 + c];
    }
    __syncthreads();
    int p0 = blockIdx.x * TP;
    const int G = 256 / TP;          // threads per position
    int pr = tid / G, seg = tid % G;
    const float4* src = (const float4*)(yin + (size_t)(p0 + pr)*64 + seg*(64/G));
#pragma unroll
    for (int j = 0; j < 16/G; j++) {
        float4 v = src[j]; int c = seg*(64/G) + j*4;
        A[(c+0)*AS + pr] = fmaxf(fmaf(v.x, sc[c+0], sb[c+0]), 0.f);
        A[(c+1)*AS + pr] = fmaxf(fmaf(v.y, sc[c+1], sb[c+1]), 0.f);
        A[(c+2)*AS + pr] = fmaxf(fmaf(v.z, sc[c+2], sb[c+2]), 0.f);
        A[(c+3)*AS + pr] = fmaxf(fmaf(v.w, sc[c+3], sb[c+3]), 0.f);
    }
    __syncthreads();
    gemm_epi<64,CO,TP>(A, Wsh, yout, ps, pq, p0);
}

// ---------------- BN stats reduce: partials -> scale/shift ----------------
template<int NB, int CO>
__global__ void k_stats(const float* __restrict__ ps, const float* __restrict__ pq,
                        const float* __restrict__ g, const float* __restrict__ bb,
                        float* bn) {
    __shared__ float ss[256], sq[256];
    int ch = blockIdx.x, tid = threadIdx.x;
    float S = 0, Q = 0;
    for (int i = tid; i < NB; i += 256) { S += ps[i*CO + ch]; Q += pq[i*CO + ch]; }
    ss[tid] = S; sq[tid] = Q; __syncthreads();
    for (int s = 128; s > 0; s >>= 1) {
        if (tid < s) { ss[tid] += ss[tid+s]; sq[tid] += sq[tid+s]; }
        __syncthreads();
    }
    if (tid == 0) {
        float cnt = (float)P_;
        float mu = ss[0]/cnt, var = sq[0]/cnt - mu*mu;
        float scv = g[ch] * rsqrtf(var + 1e-5f);
        bn[ch] = scv; bn[CO + ch] = bb[ch] - mu*scv;
    }
}

// ---------------- final BN3+ReLU+max over k ----------------
__global__ void k_max(float* __restrict__ out) {
    int m = blockIdx.x, b = blockIdx.y, o = threadIdx.x;
    float scv = g_bn3[o], shv = g_bn3[128 + o];
    size_t base = ((size_t)(b*M_ + m))*32*128 + o;
    float mx = 0.0f;
#pragma unroll 8
    for (int k = 0; k < 32; k++) {
        float v = g_y3[base + (size_t)k*128];
        mx = fmaxf(mx, fmaxf(fmaf(v, scv, shv), 0.f));
    }
    out[((size_t)b*128 + o)*M_ + m] = mx;
}

// ---------------- launch ----------------
extern "C" void kernel_launch(void* const* d_in, const int* in_sizes, int n_in,
                              void* d_out, int out_size) {
    const float* loc = (const float*)d_in[0];
    const float* nl  = (const float*)d_in[1];
    const float* ft  = (const float*)d_in[2];
    const float* W1  = (const float*)d_in[3];
    const float* g1  = (const float*)d_in[4];
    const float* b1  = (const float*)d_in[5];
    const float* W2  = (const float*)d_in[6];
    const float* g2  = (const float*)d_in[7];
    const float* b2  = (const float*)d_in[8];
    const float* W3  = (const float*)d_in[9];
    const float* g3  = (const float*)d_in[10];
    const float* b3  = (const float*)d_in[11];
    float* out = (float*)d_out;

    const int S1 = (68*132 + 68*64) * 4;   // 53312
    const int S2 = (64*132 + 64*64) * 4;   // 50176
    const int S3 = (64*68  + 64*128) * 4;  // 50176
    cudaFuncSetAttribute((const void*)k_stage1,      cudaFuncAttributeMaxDynamicSharedMemorySize, S1);
    cudaFuncSetAttribute((const void*)k_stageN<64,128>,  cudaFuncAttributeMaxDynamicSharedMemorySize, S2);
    cudaFuncSetAttribute((const void*)k_stageN<128,64>,  cudaFuncAttributeMaxDynamicSharedMemorySize, S3);

    float *y1, *y2, *y3, *p1s, *p1q, *p2s, *p2q, *p3s, *p3q, *bn1, *bn2, *bn3;
    cudaGetSymbolAddress((void**)&y1, g_y1);   cudaGetSymbolAddress((void**)&y2, g_y2);
    cudaGetSymbolAddress((void**)&y3, g_y3);
    cudaGetSymbolAddress((void**)&p1s, g_p1s); cudaGetSymbolAddress((void**)&p1q, g_p1q);
    cudaGetSymbolAddress((void**)&p2s, g_p2s); cudaGetSymbolAddress((void**)&p2q, g_p2q);
    cudaGetSymbolAddress((void**)&p3s, g_p3s); cudaGetSymbolAddress((void**)&p3q, g_p3q);
    cudaGetSymbolAddress((void**)&bn1, g_bn1); cudaGetSymbolAddress((void**)&bn2, g_bn2);
    cudaGetSymbolAddress((void**)&bn3, g_bn3);

    k_transpose<<<dim3(N_/32, 2, B_), dim3(32, 8)>>>(ft);
    k_knn<<<dim3(M_, B_), 128>>>(loc, nl);
    k_stage1<<<P_/128, 256, S1>>>(loc, nl, W1);
    k_stats<4096,64><<<64, 256>>>(p1s, p1q, g1, b1, bn1);
    k_stageN<64,128><<<P_/128, 256, S2>>>(y1, W2, bn1, y2, p2s, p2q);
    k_stats<4096,64><<<64, 256>>>(p2s, p2q, g2, b2, bn2);
    k_stageN<128,64><<<P_/64, 256, S3>>>(y2, W3, bn2, y3, p3s, p3q);
    k_stats<8192,128><<<128, 256>>>(p3s, p3q, g3, b3, bn3);
    k_max<<<dim3(M_, B_), 128>>>(out);
}